// round 15
// baseline (speedup 1.0000x reference)
#include <cuda_runtime.h>
#include <cuda_fp16.h>
#include <cstdint>
#include <math.h>

#define EPS_VAR 1e-9f
#define SMAX (4*1472)

// ---------------- scratch (static device globals; no allocation) ----------------
// Device globals are ONLY referenced from device code (never passed as kernel
// args from host: host would pass the host shadow address, ATS dereferences it).
// Arrays hold all three scales at disjoint offsets so scales can run concurrently.
__device__ float  g_scores[71565312];            // fp32 scores (all scales)
__device__ __half g_Ahi[71565312];               // softmax probs (fp16)
__device__ __half g_Qhi[13631488], g_Qlo[13631488];
__device__ __half g_Khi[13631488];
__device__ __half g_Whi[13631488];               // [V^T ; (V^2)^T]
__device__ float  g_MT[13631488];                // [M | T] outputs
__device__ float g_sum_q[3*SMAX], g_ss_q[3*SMAX], g_aq[3*SMAX], g_bq[3*SMAX];
__device__ float g_sum_k[3*SMAX], g_ss_k[3*SMAX], g_ak[3*SMAX], g_bk[3*SMAX];
__device__ float g_sum_c[3*SMAX], g_ss_c[3*SMAX], g_ac[3*SMAX], g_bc[3*SMAX];
__device__ double g_loss;

// ---------------- PTX helpers (sm_80-level baseline features only) ----------------
__device__ __forceinline__ uint32_t smem_u32(const void* p){
    uint32_t a; asm("{ .reg .u64 t; cvta.to.shared.u64 t, %1; cvt.u32.u64 %0, t; }" : "=r"(a) : "l"(p)); return a;
}
__device__ __forceinline__ void cp_async16(uint32_t dst, const void* src){
    asm volatile("cp.async.cg.shared.global [%0], [%1], 16;" :: "r"(dst), "l"(src) : "memory");
}
#define CP_COMMIT() asm volatile("cp.async.commit_group;" ::: "memory")
#define CP_WAIT(n)  asm volatile("cp.async.wait_group %0;" :: "n"(n) : "memory")

__device__ __forceinline__ void ldsm4(uint32_t* r, uint32_t addr){
    asm volatile("ldmatrix.sync.aligned.m8n8.x4.shared.b16 {%0,%1,%2,%3}, [%4];"
        : "=r"(r[0]), "=r"(r[1]), "=r"(r[2]), "=r"(r[3]) : "r"(addr));
}
__device__ __forceinline__ void ldsm2(uint32_t* r, uint32_t addr){
    asm volatile("ldmatrix.sync.aligned.m8n8.x2.shared.b16 {%0,%1}, [%2];"
        : "=r"(r[0]), "=r"(r[1]) : "r"(addr));
}
__device__ __forceinline__ void mma_f16(float* c, const uint32_t* a, const uint32_t* b){
    asm volatile("mma.sync.aligned.m16n8k16.row.col.f32.f16.f16.f32 "
        "{%0,%1,%2,%3}, {%4,%5,%6,%7}, {%8,%9}, {%0,%1,%2,%3};"
        : "+f"(c[0]), "+f"(c[1]), "+f"(c[2]), "+f"(c[3])
        : "r"(a[0]), "r"(a[1]), "r"(a[2]), "r"(a[3]), "r"(b[0]), "r"(b[1]));
}

// ---------------- small kernels ----------------
__global__ void zero_loss_kernel() { g_loss = 0.0; }

__global__ void zero_sums_kernel(int soff) {
    int i = blockIdx.x * blockDim.x + threadIdx.x;
    if (i < SMAX) {
        g_sum_q[soff + i] = 0.f; g_ss_q[soff + i] = 0.f;
        g_sum_k[soff + i] = 0.f; g_ss_k[soff + i] = 0.f;
        g_sum_c[soff + i] = 0.f; g_ss_c[soff + i] = 0.f;
    }
}

// merged stats over q (comb_c), k (comb_s), c (content); blockIdx.z selects
__global__ void stats_partial_all(const float* __restrict__ cc, const float* __restrict__ sc,
                                  const float* __restrict__ cv,
                                  int N, int C, int Cc, int soff) {
    int which = blockIdx.z;
    const float* x = (which == 0) ? cc : (which == 1) ? sc : cv;
    int Cx = (which == 2) ? C : Cc;
    float* gsum = ((which == 0) ? g_sum_q : (which == 1) ? g_sum_k : g_sum_c) + soff;
    float* gss  = ((which == 0) ? g_ss_q  : (which == 1) ? g_ss_k  : g_ss_c) + soff;
    int b = blockIdx.x, chunk = blockIdx.y;
    int r0 = chunk * 8;
    for (int c = threadIdx.x; c < Cx; c += blockDim.x) {
        float s = 0.f, ss = 0.f;
        const float* p = x + ((size_t)b * N + r0) * Cx + c;
        #pragma unroll
        for (int r = 0; r < 8; r++) {
            float v = p[(size_t)r * Cx];
            s += v; ss = fmaf(v, v, ss);
        }
        atomicAdd(&gsum[b * Cx + c], s);
        atomicAdd(&gss[b * Cx + c], ss);
    }
}

__global__ void stats_final_all(int N, int C, int Cc, int B, int soff) {
    int which = blockIdx.y;
    int Cx = (which == 2) ? C : Cc;
    const float* gsum = ((which == 0) ? g_sum_q : (which == 1) ? g_sum_k : g_sum_c) + soff;
    const float* gss  = ((which == 0) ? g_ss_q  : (which == 1) ? g_ss_k  : g_ss_c) + soff;
    float* ga = ((which == 0) ? g_aq : (which == 1) ? g_ak : g_ac) + soff;
    float* gb = ((which == 0) ? g_bq : (which == 1) ? g_bk : g_bc) + soff;
    int i = blockIdx.x * blockDim.x + threadIdx.x;
    if (i < B * Cx) {
        float invN = 1.0f / (float)N;
        float mean = gsum[i] * invN;
        float var  = gss[i] * invN - mean * mean;
        float r = rsqrtf(var + 1e-5f);
        ga[i] = r;
        gb[i] = -mean * r;
    }
}

// normalize + split fp32 -> fp16. Q gets hi+lo, K gets hi only (2-term QK).
// blockIdx.y: 0 = comb_c -> Q, 1 = comb_s -> K
__global__ void prep_split_affine(const float* __restrict__ xq, const float* __restrict__ xk,
                                  int total, int C, int perBatch, int soff, size_t qoff) {
    int which = blockIdx.y;
    const float* x  = (which == 0) ? xq : xk;
    const float* ga = ((which == 0) ? g_aq : g_ak) + soff;
    const float* gb = ((which == 0) ? g_bq : g_bk) + soff;
    int i = blockIdx.x * blockDim.x + threadIdx.x;
    if (i >= total) return;
    int b = i / perBatch;
    int ch = i % C;
    float y = fmaf(x[i], ga[b * C + ch], gb[b * C + ch]);
    __half h = __float2half(y);
    if (which == 0) {
        g_Qhi[qoff + i] = h;
        g_Qlo[qoff + i] = __float2half(y - __half2float(h));
    } else {
        g_Khi[qoff + i] = h;
    }
}

// W = [V^T ; (V^2)^T]  (2C x N per batch), fp16
__global__ void prep_w(const float* __restrict__ v, int N, int C, size_t woff) {
    __shared__ float tile[32][33];
    int b = blockIdx.z;
    int j0 = blockIdx.x * 32, c0 = blockIdx.y * 32;
    int tx = threadIdx.x, ty = threadIdx.y;  // 32 x 8
    const float* vb = v + (size_t)b * N * C;
    #pragma unroll
    for (int r = 0; r < 4; r++)
        tile[ty + 8 * r][tx] = vb[(size_t)(j0 + ty + 8 * r) * C + c0 + tx];
    __syncthreads();
    __half* w = g_Whi + woff + (size_t)b * 2 * C * N;
    #pragma unroll
    for (int r = 0; r < 4; r++) {
        int c = c0 + ty + 8 * r, j = j0 + tx;
        float val = tile[tx][ty + 8 * r];
        w[(size_t)c * N + j] = __float2half(val);
        w[(size_t)(C + c) * N + j] = __float2half(val * val);
    }
}

// ---------------- mma.sync fp16 GEMM: D = X * Y^T ----------------
// 128x256 block tile, 512 threads = 16 warps of 64x32, KCH=16, TROWB=48.
// MODE 0 (2-term): tiles/stage = Qhi + Qlo + K(256 rows) = 4x6144 = 24576B;
//                  x2 stages = 49152B (exactly the 48KB no-opt-in limit).
// MODE 1 (1-term): tiles/stage = A + W(256 rows) = 3x6144 = 18432B; x2 = 36864B.
// Per-output-tile traffic: MODE0 2/256+1/128 (was 3/128, -33%); MODE1 1/256+1/128 (-25%).
// Bank-conflict check (8-row ldmatrix phase): words 12r mod 32 all distinct.

template<int MODE>
__global__ __launch_bounds__(512)
void gemm_f16(int Mg, int Ng, int Kg, size_t xoff, size_t yoff, size_t doff) {
    constexpr int NT = (MODE == 0) ? 4 : 3;       // logical 128-row tiles per stage
    constexpr int KCH = 16;
    constexpr int TROWB = 48;
    constexpr int TILE_BYTES = 128 * TROWB;       // 6144
    constexpr int STAGE_BYTES = NT * TILE_BYTES;
    extern __shared__ char smem[];
    uint32_t sb = smem_u32(smem);
    int tid = threadIdx.x;
    int wid = tid >> 5, lane = tid & 31;
    int g = lane >> 2, t = lane & 3;
    int warp_m0 = (wid >> 3) << 6;   // 0 or 64
    int warp_n0 = (wid & 7) << 5;    // 0..224
    int b = blockIdx.z;
    int bi = blockIdx.y * 128, bj = blockIdx.x * 256;

    const __half* Xhi = ((MODE == 0) ? g_Qhi : g_Ahi) + xoff;
    const __half* Xlo = g_Qlo + xoff;                       // MODE 0 only
    const __half* Yhi = ((MODE == 0) ? g_Khi : g_Whi) + yoff;
    float* D = ((MODE == 0) ? g_scores : g_MT) + doff;

    const __half* yb = Yhi + (size_t)b * Ng * Kg + (size_t)bj * Kg;
    const __half* srcs[NT];
    srcs[0] = Xhi + (size_t)b * Mg * Kg + (size_t)bi * Kg;
    if (MODE == 0) {
        srcs[1] = Xlo + (size_t)b * Mg * Kg + (size_t)bi * Kg;
    }
    srcs[NT - 2] = yb;                    // Y rows [0,128)
    srcs[NT - 1] = yb + (size_t)128 * Kg; // Y rows [128,256)

    float acc[4][4][4];
    #pragma unroll
    for (int i = 0; i < 4; i++)
        #pragma unroll
        for (int j = 0; j < 4; j++)
            #pragma unroll
            for (int k = 0; k < 4; k++) acc[i][j][k] = 0.f;

    int nch = Kg / KCH;

    uint32_t a_off = (uint32_t)((warp_m0 + (lane & 15)) * TROWB + (lane >> 4) * 16);
    // B region: 256 contiguous rows starting at tile index NT-2
    uint32_t b_off = (uint32_t)((warp_n0 + (lane & 7)) * TROWB + ((lane >> 3) & 1) * 16);

    auto load_chunk = [&](uint32_t sbase, int k0) {
        constexpr int TOTAL = NT * 256;       // 16B vectors per stage (256/tile)
        #pragma unroll
        for (int v = 0; v < (TOTAL + 511) / 512; v++) {
            int idx = tid + v * 512;
            if (TOTAL % 512 != 0 && idx >= TOTAL) break;
            int a = idx >> 8, rem = idx & 255;
            int r = rem >> 1, h = rem & 1;
            cp_async16(sbase + a * TILE_BYTES + r * TROWB + h * 16,
                       srcs[a] + (size_t)r * Kg + k0 + h * 8);
        }
    };

    load_chunk(sb, 0);
    CP_COMMIT();

    for (int i = 0; i < nch; i++) {
        uint32_t stage = (uint32_t)(i & 1) * STAGE_BYTES;
        if (i + 1 < nch) {
            load_chunk(sb + (uint32_t)((i + 1) & 1) * STAGE_BYTES, (i + 1) * KCH);
            CP_COMMIT();
            CP_WAIT(1);
        } else {
            CP_WAIT(0);
        }
        __syncthreads();

        uint32_t sA  = sb + stage;
        uint32_t sB  = sA + (uint32_t)(NT - 2) * TILE_BYTES;   // 256-row B region
        if (MODE == 0) {
            uint32_t sAl = sA + TILE_BYTES;
            uint32_t ah[4][4], al[4][4], bh[4][2];
            #pragma unroll
            for (int mi = 0; mi < 4; mi++) {
                uint32_t o = a_off + mi * 16 * TROWB;
                ldsm4(ah[mi], sA + o);
                ldsm4(al[mi], sAl + o);
            }
            #pragma unroll
            for (int ni = 0; ni < 4; ni++)
                ldsm2(bh[ni], sB + b_off + ni * 8 * TROWB);
            #pragma unroll
            for (int mi = 0; mi < 4; mi++)
                #pragma unroll
                for (int ni = 0; ni < 4; ni++) {
                    mma_f16(acc[mi][ni], ah[mi], bh[ni]);
                    mma_f16(acc[mi][ni], al[mi], bh[ni]);
                }
        } else {
            uint32_t ah[4][4], bh[4][2];
            #pragma unroll
            for (int mi = 0; mi < 4; mi++)
                ldsm4(ah[mi], sA + a_off + mi * 16 * TROWB);
            #pragma unroll
            for (int ni = 0; ni < 4; ni++)
                ldsm2(bh[ni], sB + b_off + ni * 8 * TROWB);
            #pragma unroll
            for (int mi = 0; mi < 4; mi++)
                #pragma unroll
                for (int ni = 0; ni < 4; ni++)
                    mma_f16(acc[mi][ni], ah[mi], bh[ni]);
        }
        __syncthreads();
    }

    float* db = D + (size_t)b * Mg * Ng;
    #pragma unroll
    for (int mi = 0; mi < 4; mi++) {
        int gr = bi + warp_m0 + mi * 16 + g;
        #pragma unroll
        for (int ni = 0; ni < 4; ni++) {
            int gc = bj + warp_n0 + ni * 8 + t * 2;
            float2 v0 = make_float2(acc[mi][ni][0], acc[mi][ni][1]);
            float2 v1 = make_float2(acc[mi][ni][2], acc[mi][ni][3]);
            *reinterpret_cast<float2*>(db + (size_t)gr * Ng + gc) = v0;
            *reinterpret_cast<float2*>(db + (size_t)(gr + 8) * Ng + gc) = v1;
        }
    }
}

// ---------------- row softmax: fp32 scores -> fp16 probs (vectorized) ----------------
__global__ void softmax_rows(int N, size_t scoff) {
    extern __shared__ float srow[];
    __shared__ float red[33];
    size_t row = blockIdx.x;
    const float4* p4 = reinterpret_cast<const float4*>(g_scores + scoff + row * (size_t)N);
    int tid = threadIdx.x, bd = blockDim.x;
    int n4 = N >> 2;

    float m = -1e30f;
    for (int j = tid; j < n4; j += bd) {
        float4 v = p4[j];
        *reinterpret_cast<float4*>(srow + 4 * j) = v;
        m = fmaxf(m, fmaxf(fmaxf(v.x, v.y), fmaxf(v.z, v.w)));
    }
    #pragma unroll
    for (int o = 16; o > 0; o >>= 1) m = fmaxf(m, __shfl_xor_sync(0xffffffffu, m, o));
    if ((tid & 31) == 0) red[tid >> 5] = m;
    __syncthreads();
    if (tid < 32) {
        float v = (tid < (bd >> 5)) ? red[tid] : -1e30f;
        #pragma unroll
        for (int o = 16; o > 0; o >>= 1) v = fmaxf(v, __shfl_xor_sync(0xffffffffu, v, o));
        if (tid == 0) red[32] = v;
    }
    __syncthreads();
    m = red[32];

    float s = 0.f;
    for (int j = tid; j < n4; j += bd) {
        float4 v = *reinterpret_cast<float4*>(srow + 4 * j);
        v.x = __expf(v.x - m); v.y = __expf(v.y - m);
        v.z = __expf(v.z - m); v.w = __expf(v.w - m);
        *reinterpret_cast<float4*>(srow + 4 * j) = v;
        s += (v.x + v.y) + (v.z + v.w);
    }
    __syncthreads();
    #pragma unroll
    for (int o = 16; o > 0; o >>= 1) s += __shfl_xor_sync(0xffffffffu, s, o);
    if ((tid & 31) == 0) red[tid >> 5] = s;
    __syncthreads();
    if (tid < 32) {
        float v = (tid < (bd >> 5)) ? red[tid] : 0.f;
        #pragma unroll
        for (int o = 16; o > 0; o >>= 1) v += __shfl_xor_sync(0xffffffffu, v, o);
        if (tid == 0) red[32] = v;
    }
    __syncthreads();
    float inv = 1.0f / red[32];
    __half2* a2 = reinterpret_cast<__half2*>(g_Ahi + scoff + row * (size_t)N);
    int n2 = N >> 1;
    for (int j = tid; j < n2; j += bd)
        a2[j] = __floats2half2_rn(srow[2 * j] * inv, srow[2 * j + 1] * inv);
}

// ---------------- loss epilogue from [M|T] ----------------
__global__ void loss_epilogue(const float* __restrict__ cin, const float* __restrict__ cs,
                              int N, int C, float inv_count, int total,
                              size_t mtoff, int soff) {
    int i = blockIdx.x * blockDim.x + threadIdx.x;
    float local = 0.f;
    if (i < total) {
        int c = i % C;
        int r = i / C;          // = b*N + n
        int b = r / N;
        const float* mt = g_MT + mtoff;
        float m = mt[(size_t)r * 2 * C + c];
        float t = mt[(size_t)r * 2 * C + C + c];
        float s2 = t - m * m;
        float s = sqrtf(fmaxf(s2, EPS_VAR));
        float nc = fmaf(cin[i], g_ac[soff + b * C + c], g_bc[soff + b * C + c]);
        float aat = fmaf(s, nc, m);
        float d = cs[i] - aat;
        local = d * d * inv_count;
    }
    #pragma unroll
    for (int o = 16; o > 0; o >>= 1) local += __shfl_xor_sync(0xffffffffu, local, o);
    __shared__ float red[8];
    int tid = threadIdx.x;
    if ((tid & 31) == 0) red[tid >> 5] = local;
    __syncthreads();
    if (tid == 0) {
        float t = 0.f;
        #pragma unroll
        for (int k = 0; k < 8; k++) t += red[k];
        atomicAdd(&g_loss, (double)t);
    }
}

__global__ void write_out_kernel(float* out) { out[0] = (float)g_loss; }

// ---------------- host launcher ----------------
struct ScaleP { int i_cs, i_c, i_s, i_cc, i_sc, N, C, Cc; size_t qoff, woff, scoff; int soff; };

static void run_scale(const ScaleP& p, void* const* d_in, cudaStream_t st) {
    const int B = 4;
    const float* cs = (const float*)d_in[p.i_cs];
    const float* c  = (const float*)d_in[p.i_c];
    const float* stp= (const float*)d_in[p.i_s];
    const float* cc = (const float*)d_in[p.i_cc];
    const float* sc = (const float*)d_in[p.i_sc];

    zero_sums_kernel<<<(SMAX + 255) / 256, 256, 0, st>>>(p.soff);

    dim3 gs(B, p.N / 8, 3);
    stats_partial_all<<<gs, 256, 0, st>>>(cc, sc, c, p.N, p.C, p.Cc, p.soff);
    dim3 gf((B * p.Cc + 255) / 256, 3);
    stats_final_all<<<gf, 256, 0, st>>>(p.N, p.C, p.Cc, B, p.soff);

    int totQ = B * p.N * p.Cc;
    dim3 gp((totQ + 255) / 256, 2);
    prep_split_affine<<<gp, 256, 0, st>>>(cc, sc, totQ, p.Cc, p.N * p.Cc, p.soff, p.qoff);

    dim3 gw(p.N / 32, p.C / 32, B);
    prep_w<<<gw, dim3(32, 8), 0, st>>>(stp, p.N, p.C, p.woff);

    dim3 g1(p.N / 256, p.N / 128, B);
    gemm_f16<0><<<g1, 512, 2 * 4 * 128 * 48, st>>>(p.N, p.N, p.Cc, p.qoff, p.qoff, p.scoff);

    softmax_rows<<<B * p.N, 256, p.N * sizeof(float), st>>>(p.N, p.scoff);

    dim3 g2((2 * p.C) / 256, p.N / 128, B);
    gemm_f16<1><<<g2, 512, 2 * 3 * 128 * 48, st>>>(p.N, 2 * p.C, p.N, p.scoff, p.woff, p.woff);

    int tot = B * p.N * p.C;
    float inv_count = 1.0f / (float)tot;
    loss_epilogue<<<(tot + 255) / 256, 256, 0, st>>>(c, cs, p.N, p.C, inv_count, tot, p.woff, p.soff);
}

extern "C" void kernel_launch(void* const* d_in, const int* in_sizes, int n_in,
                              void* d_out, int out_size) {
    (void)in_sizes; (void)n_in; (void)out_size;

    static bool s_init = false;
    static cudaStream_t s_aux;
    static cudaEvent_t ev_fork, ev_join;
    if (!s_init) {
        cudaStreamCreateWithFlags(&s_aux, cudaStreamNonBlocking);
        cudaEventCreateWithFlags(&ev_fork, cudaEventDisableTiming);
        cudaEventCreateWithFlags(&ev_join, cudaEventDisableTiming);
        s_init = true;
    }

    // per-scale buffer offsets (elements)
    ScaleP ps[3] = {
        { 0, 1, 2, 3, 4, 4096, 256,  448, 0,        0,        0,        0      },
        { 5, 6, 7, 8, 9, 1024, 512,  960, 7340032,  8388608,  67108864, SMAX   },
        {10,11,12,13,14, 256, 512, 1472, 11272192, 12582912, 71303168, 2*SMAX },
    };

    zero_loss_kernel<<<1, 1>>>();

    // fork aux stream off the capture-origin (default) stream
    cudaEventRecord(ev_fork, 0);
    cudaStreamWaitEvent(s_aux, ev_fork, 0);

    run_scale(ps[0], d_in, 0);       // big scale on main stream
    run_scale(ps[1], d_in, s_aux);   // smaller scales overlap on aux
    run_scale(ps[2], d_in, s_aux);

    // join
    cudaEventRecord(ev_join, s_aux);
    cudaStreamWaitEvent(0, ev_join, 0);

    write_out_kernel<<<1, 1>>>((float*)d_out);
}

// round 16
// speedup vs baseline: 1.0614x; 1.0614x over previous
#include <cuda_runtime.h>
#include <cuda_fp16.h>
#include <cstdint>
#include <math.h>

#define EPS_VAR 1e-9f
#define SMAX (4*1472)

// ---------------- scratch (static device globals; no allocation) ----------------
// Device globals are ONLY referenced from device code (never passed as kernel
// args from host: host would pass the host shadow address, ATS dereferences it).
// Arrays hold all three scales at disjoint offsets so scales can run concurrently.
__device__ float  g_scores[71565312];            // fp32 scores (all scales)
__device__ __half g_Ahi[71565312];               // softmax probs (fp16)
__device__ __half g_Qhi[13631488], g_Qlo[13631488];
__device__ __half g_Khi[13631488];
__device__ __half g_Whi[13631488];               // interleaved [V_c ; V^2_c] rows
__device__ float g_sum_q[3*SMAX], g_ss_q[3*SMAX], g_aq[3*SMAX], g_bq[3*SMAX];
__device__ float g_sum_k[3*SMAX], g_ss_k[3*SMAX], g_ak[3*SMAX], g_bk[3*SMAX];
__device__ float g_sum_c[3*SMAX], g_ss_c[3*SMAX], g_ac[3*SMAX], g_bc[3*SMAX];
__device__ double g_loss;

// ---------------- PTX helpers (sm_80-level baseline features only) ----------------
__device__ __forceinline__ uint32_t smem_u32(const void* p){
    uint32_t a; asm("{ .reg .u64 t; cvta.to.shared.u64 t, %1; cvt.u32.u64 %0, t; }" : "=r"(a) : "l"(p)); return a;
}
__device__ __forceinline__ void cp_async16(uint32_t dst, const void* src){
    asm volatile("cp.async.cg.shared.global [%0], [%1], 16;" :: "r"(dst), "l"(src) : "memory");
}
#define CP_COMMIT() asm volatile("cp.async.commit_group;" ::: "memory")
#define CP_WAIT(n)  asm volatile("cp.async.wait_group %0;" :: "n"(n) : "memory")

__device__ __forceinline__ void ldsm4(uint32_t* r, uint32_t addr){
    asm volatile("ldmatrix.sync.aligned.m8n8.x4.shared.b16 {%0,%1,%2,%3}, [%4];"
        : "=r"(r[0]), "=r"(r[1]), "=r"(r[2]), "=r"(r[3]) : "r"(addr));
}
__device__ __forceinline__ void ldsm2(uint32_t* r, uint32_t addr){
    asm volatile("ldmatrix.sync.aligned.m8n8.x2.shared.b16 {%0,%1}, [%2];"
        : "=r"(r[0]), "=r"(r[1]) : "r"(addr));
}
__device__ __forceinline__ void mma_f16(float* c, const uint32_t* a, const uint32_t* b){
    asm volatile("mma.sync.aligned.m16n8k16.row.col.f32.f16.f16.f32 "
        "{%0,%1,%2,%3}, {%4,%5,%6,%7}, {%8,%9}, {%0,%1,%2,%3};"
        : "+f"(c[0]), "+f"(c[1]), "+f"(c[2]), "+f"(c[3])
        : "r"(a[0]), "r"(a[1]), "r"(a[2]), "r"(a[3]), "r"(b[0]), "r"(b[1]));
}

// ---------------- small kernels ----------------
__global__ void zero_loss_kernel() { g_loss = 0.0; }

__global__ void zero_sums_kernel(int soff) {
    int i = blockIdx.x * blockDim.x + threadIdx.x;
    if (i < SMAX) {
        g_sum_q[soff + i] = 0.f; g_ss_q[soff + i] = 0.f;
        g_sum_k[soff + i] = 0.f; g_ss_k[soff + i] = 0.f;
        g_sum_c[soff + i] = 0.f; g_ss_c[soff + i] = 0.f;
    }
}

// merged stats over q (comb_c), k (comb_s), c (content); blockIdx.z selects
__global__ void stats_partial_all(const float* __restrict__ cc, const float* __restrict__ sc,
                                  const float* __restrict__ cv,
                                  int N, int C, int Cc, int soff) {
    int which = blockIdx.z;
    const float* x = (which == 0) ? cc : (which == 1) ? sc : cv;
    int Cx = (which == 2) ? C : Cc;
    float* gsum = ((which == 0) ? g_sum_q : (which == 1) ? g_sum_k : g_sum_c) + soff;
    float* gss  = ((which == 0) ? g_ss_q  : (which == 1) ? g_ss_k  : g_ss_c) + soff;
    int b = blockIdx.x, chunk = blockIdx.y;
    int r0 = chunk * 8;
    for (int c = threadIdx.x; c < Cx; c += blockDim.x) {
        float s = 0.f, ss = 0.f;
        const float* p = x + ((size_t)b * N + r0) * Cx + c;
        #pragma unroll
        for (int r = 0; r < 8; r++) {
            float v = p[(size_t)r * Cx];
            s += v; ss = fmaf(v, v, ss);
        }
        atomicAdd(&gsum[b * Cx + c], s);
        atomicAdd(&gss[b * Cx + c], ss);
    }
}

__global__ void stats_final_all(int N, int C, int Cc, int B, int soff) {
    int which = blockIdx.y;
    int Cx = (which == 2) ? C : Cc;
    const float* gsum = ((which == 0) ? g_sum_q : (which == 1) ? g_sum_k : g_sum_c) + soff;
    const float* gss  = ((which == 0) ? g_ss_q  : (which == 1) ? g_ss_k  : g_ss_c) + soff;
    float* ga = ((which == 0) ? g_aq : (which == 1) ? g_ak : g_ac) + soff;
    float* gb = ((which == 0) ? g_bq : (which == 1) ? g_bk : g_bc) + soff;
    int i = blockIdx.x * blockDim.x + threadIdx.x;
    if (i < B * Cx) {
        float invN = 1.0f / (float)N;
        float mean = gsum[i] * invN;
        float var  = gss[i] * invN - mean * mean;
        float r = rsqrtf(var + 1e-5f);
        ga[i] = r;
        gb[i] = -mean * r;
    }
}

// normalize + split fp32 -> fp16. Q gets hi+lo, K gets hi only (2-term QK).
// blockIdx.y: 0 = comb_c -> Q, 1 = comb_s -> K
__global__ void prep_split_affine(const float* __restrict__ xq, const float* __restrict__ xk,
                                  int total, int C, int perBatch, int soff, size_t qoff) {
    int which = blockIdx.y;
    const float* x  = (which == 0) ? xq : xk;
    const float* ga = ((which == 0) ? g_aq : g_ak) + soff;
    const float* gb = ((which == 0) ? g_bq : g_bk) + soff;
    int i = blockIdx.x * blockDim.x + threadIdx.x;
    if (i >= total) return;
    int b = i / perBatch;
    int ch = i % C;
    float y = fmaf(x[i], ga[b * C + ch], gb[b * C + ch]);
    __half h = __float2half(y);
    if (which == 0) {
        g_Qhi[qoff + i] = h;
        g_Qlo[qoff + i] = __float2half(y - __half2float(h));
    } else {
        g_Khi[qoff + i] = h;
    }
}

// W interleaved: row 2c = V^T_c, row 2c+1 = (V^2)^T_c  (2C x N per batch), fp16
__global__ void prep_w(const float* __restrict__ v, int N, int C, size_t woff) {
    __shared__ float tile[32][33];
    int b = blockIdx.z;
    int j0 = blockIdx.x * 32, c0 = blockIdx.y * 32;
    int tx = threadIdx.x, ty = threadIdx.y;  // 32 x 8
    const float* vb = v + (size_t)b * N * C;
    #pragma unroll
    for (int r = 0; r < 4; r++)
        tile[ty + 8 * r][tx] = vb[(size_t)(j0 + ty + 8 * r) * C + c0 + tx];
    __syncthreads();
    __half* w = g_Whi + woff + (size_t)b * 2 * C * N;
    #pragma unroll
    for (int r = 0; r < 4; r++) {
        int c = c0 + ty + 8 * r, j = j0 + tx;
        float val = tile[tx][ty + 8 * r];
        w[(size_t)(2 * c) * N + j] = __float2half(val);
        w[(size_t)(2 * c + 1) * N + j] = __float2half(val * val);
    }
}

// ---------------- mma.sync fp16 GEMM: D = X * Y^T ----------------
// MODE 0 (2-term): X = Qn hi/lo (Kg=Cc), Y = Kn hi, D = g_scores (fp32).
//                  3 tiles/stage, KCH=16, TROWB=48 -> 36864B smem.
// MODE 1 (1-term): X = A = g_Ahi (Kg=N), Y = W interleaved; FUSED LOSS epilogue
//                  (no D tensor written). 2 tiles/stage, KCH=32, TROWB=80 -> 40960B.
// Both fit the 48KB default dynamic-smem limit: NO cudaFuncSetAttribute needed.
// Bank-conflict check (8-row ldmatrix phase): TROWB=48 -> words 12r mod 32
// distinct; TROWB=80 -> 20r mod 32 distinct.

template<int MODE>
__global__ __launch_bounds__(256)
void gemm_f16(int Mg, int Ng, int Kg, size_t xoff, size_t yoff, size_t doff,
              const float* __restrict__ cin, const float* __restrict__ cs,
              float inv_count, int soff) {
    constexpr int NT = (MODE == 0) ? 3 : 2;
    constexpr int KCH = (MODE == 0) ? 16 : 32;
    constexpr int TROWB = (MODE == 0) ? 48 : 80;
    constexpr int TILE_BYTES = 128 * TROWB;
    constexpr int STAGE_BYTES = NT * TILE_BYTES;
    constexpr int NVEC = 128 * KCH / 8;           // 16B vectors per tile
    extern __shared__ char smem[];
    uint32_t sb = smem_u32(smem);
    int tid = threadIdx.x;
    int wid = tid >> 5, lane = tid & 31;
    int g = lane >> 2, t = lane & 3;
    int warp_m0 = (wid >> 2) << 6;   // 0 or 64
    int warp_n0 = (wid & 3) << 5;    // 0,32,64,96
    int b = blockIdx.z;
    int bi = blockIdx.y * 128, bj = blockIdx.x * 128;

    const __half* Xhi = ((MODE == 0) ? g_Qhi : g_Ahi) + xoff;
    const __half* Xlo = g_Qlo + xoff;                       // MODE 0 only
    const __half* Yhi = ((MODE == 0) ? g_Khi : g_Whi) + yoff;

    const __half* srcs[NT];
    srcs[0] = Xhi + (size_t)b * Mg * Kg + (size_t)bi * Kg;
    if (MODE == 0) {
        srcs[1] = Xlo + (size_t)b * Mg * Kg + (size_t)bi * Kg;
    }
    srcs[NT - 1] = Yhi + (size_t)b * Ng * Kg + (size_t)bj * Kg;

    float acc[4][4][4];
    #pragma unroll
    for (int i = 0; i < 4; i++)
        #pragma unroll
        for (int j = 0; j < 4; j++)
            #pragma unroll
            for (int k = 0; k < 4; k++) acc[i][j][k] = 0.f;

    int nch = Kg / KCH;

    uint32_t a_off = (uint32_t)((warp_m0 + (lane & 15)) * TROWB + (lane >> 4) * 16);
    uint32_t b_off = (uint32_t)((warp_n0 + (lane & 7)) * TROWB + ((lane >> 3) & 1) * 16);

    auto load_chunk = [&](uint32_t sbase, int k0) {
        constexpr int HPR = KCH / 8;          // 16B halves per row
        #pragma unroll
        for (int a = 0; a < NT; a++) {
            #pragma unroll
            for (int v = 0; v < NVEC / 256; v++) {
                int idx = tid + v * 256;
                int r = idx / HPR, h = idx % HPR;
                cp_async16(sbase + a * TILE_BYTES + r * TROWB + h * 16,
                           srcs[a] + (size_t)r * Kg + k0 + h * 8);
            }
        }
    };

    load_chunk(sb, 0);
    CP_COMMIT();

    for (int i = 0; i < nch; i++) {
        uint32_t stage = (uint32_t)(i & 1) * STAGE_BYTES;
        if (i + 1 < nch) {
            load_chunk(sb + (uint32_t)((i + 1) & 1) * STAGE_BYTES, (i + 1) * KCH);
            CP_COMMIT();
            CP_WAIT(1);
        } else {
            CP_WAIT(0);
        }
        __syncthreads();

        #pragma unroll
        for (int ks = 0; ks < KCH / 16; ks++) {
            uint32_t kso = (uint32_t)(ks * 32);
            if (MODE == 0) {
                uint32_t sAh = sb + stage;
                uint32_t sAl = sAh + TILE_BYTES;
                uint32_t sBh = sAl + TILE_BYTES;
                uint32_t ah[4][4], al[4][4], bh[4][2];
                #pragma unroll
                for (int mi = 0; mi < 4; mi++) {
                    uint32_t o = a_off + kso + mi * 16 * TROWB;
                    ldsm4(ah[mi], sAh + o);
                    ldsm4(al[mi], sAl + o);
                }
                #pragma unroll
                for (int ni = 0; ni < 4; ni++)
                    ldsm2(bh[ni], sBh + b_off + kso + ni * 8 * TROWB);
                #pragma unroll
                for (int mi = 0; mi < 4; mi++)
                    #pragma unroll
                    for (int ni = 0; ni < 4; ni++) {
                        mma_f16(acc[mi][ni], ah[mi], bh[ni]);
                        mma_f16(acc[mi][ni], al[mi], bh[ni]);
                    }
            } else {
                uint32_t sAh = sb + stage;
                uint32_t sBh = sAh + TILE_BYTES;
                uint32_t ah[4][4], bh[4][2];
                #pragma unroll
                for (int mi = 0; mi < 4; mi++)
                    ldsm4(ah[mi], sAh + a_off + kso + mi * 16 * TROWB);
                #pragma unroll
                for (int ni = 0; ni < 4; ni++)
                    ldsm2(bh[ni], sBh + b_off + kso + ni * 8 * TROWB);
                #pragma unroll
                for (int mi = 0; mi < 4; mi++)
                    #pragma unroll
                    for (int ni = 0; ni < 4; ni++)
                        mma_f16(acc[mi][ni], ah[mi], bh[ni]);
            }
        }
        __syncthreads();
    }

    if (MODE == 0) {
        float* db = g_scores + doff + (size_t)b * Mg * Ng;
        #pragma unroll
        for (int mi = 0; mi < 4; mi++) {
            int gr = bi + warp_m0 + mi * 16 + g;
            #pragma unroll
            for (int ni = 0; ni < 4; ni++) {
                int gc = bj + warp_n0 + ni * 8 + t * 2;
                float2 v0 = make_float2(acc[mi][ni][0], acc[mi][ni][1]);
                float2 v1 = make_float2(acc[mi][ni][2], acc[mi][ni][3]);
                *reinterpret_cast<float2*>(db + (size_t)gr * Ng + gc) = v0;
                *reinterpret_cast<float2*>(db + (size_t)(gr + 8) * Ng + gc) = v1;
            }
        }
    } else {
        // fused loss: acc pairs are (M_c, T_c) for channel c = gc/2 thanks to
        // the interleaved W layout. Cch = Ng/2.
        int Cch = Ng >> 1;
        const float* ga = g_ac + soff + b * Cch;
        const float* gbv = g_bc + soff + b * Cch;
        const float* cinb = cin + (size_t)b * Mg * Cch;
        const float* csb  = cs  + (size_t)b * Mg * Cch;
        float local = 0.f;
        #pragma unroll
        for (int mi = 0; mi < 4; mi++) {
            int gr = bi + warp_m0 + mi * 16 + g;
            #pragma unroll
            for (int ni = 0; ni < 4; ni++) {
                int c = (bj + warp_n0 + ni * 8 + t * 2) >> 1;
                float a_ = ga[c], b_ = gbv[c];
                {
                    float m = acc[mi][ni][0], tt = acc[mi][ni][1];
                    float s = sqrtf(fmaxf(tt - m * m, EPS_VAR));
                    size_t off = (size_t)gr * Cch + c;
                    float nc = fmaf(cinb[off], a_, b_);
                    float d = csb[off] - fmaf(s, nc, m);
                    local = fmaf(d, d, local);
                }
                {
                    float m = acc[mi][ni][2], tt = acc[mi][ni][3];
                    float s = sqrtf(fmaxf(tt - m * m, EPS_VAR));
                    size_t off = (size_t)(gr + 8) * Cch + c;
                    float nc = fmaf(cinb[off], a_, b_);
                    float d = csb[off] - fmaf(s, nc, m);
                    local = fmaf(d, d, local);
                }
            }
        }
        local *= inv_count;
        #pragma unroll
        for (int o = 16; o > 0; o >>= 1) local += __shfl_xor_sync(0xffffffffu, local, o);
        __shared__ float red[8];
        if (lane == 0) red[wid] = local;
        __syncthreads();
        if (tid == 0) {
            float tt = 0.f;
            #pragma unroll
            for (int k = 0; k < 8; k++) tt += red[k];
            atomicAdd(&g_loss, (double)tt);
        }
    }
}

// ---------------- row softmax: fp32 scores -> fp16 probs (vectorized) ----------------
__global__ void softmax_rows(int N, size_t scoff) {
    extern __shared__ float srow[];
    __shared__ float red[33];
    size_t row = blockIdx.x;
    const float4* p4 = reinterpret_cast<const float4*>(g_scores + scoff + row * (size_t)N);
    int tid = threadIdx.x, bd = blockDim.x;
    int n4 = N >> 2;

    float m = -1e30f;
    for (int j = tid; j < n4; j += bd) {
        float4 v = p4[j];
        *reinterpret_cast<float4*>(srow + 4 * j) = v;
        m = fmaxf(m, fmaxf(fmaxf(v.x, v.y), fmaxf(v.z, v.w)));
    }
    #pragma unroll
    for (int o = 16; o > 0; o >>= 1) m = fmaxf(m, __shfl_xor_sync(0xffffffffu, m, o));
    if ((tid & 31) == 0) red[tid >> 5] = m;
    __syncthreads();
    if (tid < 32) {
        float v = (tid < (bd >> 5)) ? red[tid] : -1e30f;
        #pragma unroll
        for (int o = 16; o > 0; o >>= 1) v = fmaxf(v, __shfl_xor_sync(0xffffffffu, v, o));
        if (tid == 0) red[32] = v;
    }
    __syncthreads();
    m = red[32];

    float s = 0.f;
    for (int j = tid; j < n4; j += bd) {
        float4 v = *reinterpret_cast<float4*>(srow + 4 * j);
        v.x = __expf(v.x - m); v.y = __expf(v.y - m);
        v.z = __expf(v.z - m); v.w = __expf(v.w - m);
        *reinterpret_cast<float4*>(srow + 4 * j) = v;
        s += (v.x + v.y) + (v.z + v.w);
    }
    __syncthreads();
    #pragma unroll
    for (int o = 16; o > 0; o >>= 1) s += __shfl_xor_sync(0xffffffffu, s, o);
    if ((tid & 31) == 0) red[tid >> 5] = s;
    __syncthreads();
    if (tid < 32) {
        float v = (tid < (bd >> 5)) ? red[tid] : 0.f;
        #pragma unroll
        for (int o = 16; o > 0; o >>= 1) v += __shfl_xor_sync(0xffffffffu, v, o);
        if (tid == 0) red[32] = v;
    }
    __syncthreads();
    float inv = 1.0f / red[32];
    __half2* a2 = reinterpret_cast<__half2*>(g_Ahi + scoff + row * (size_t)N);
    int n2 = N >> 1;
    for (int j = tid; j < n2; j += bd)
        a2[j] = __floats2half2_rn(srow[2 * j] * inv, srow[2 * j + 1] * inv);
}

__global__ void write_out_kernel(float* out) { out[0] = (float)g_loss; }

// ---------------- host launcher ----------------
struct ScaleP { int i_cs, i_c, i_s, i_cc, i_sc, N, C, Cc; size_t qoff, woff, scoff; int soff; };

static void run_scale(const ScaleP& p, void* const* d_in, cudaStream_t st) {
    const int B = 4;
    const float* cs = (const float*)d_in[p.i_cs];
    const float* c  = (const float*)d_in[p.i_c];
    const float* stp= (const float*)d_in[p.i_s];
    const float* cc = (const float*)d_in[p.i_cc];
    const float* sc = (const float*)d_in[p.i_sc];

    zero_sums_kernel<<<(SMAX + 255) / 256, 256, 0, st>>>(p.soff);

    dim3 gs(B, p.N / 8, 3);
    stats_partial_all<<<gs, 256, 0, st>>>(cc, sc, c, p.N, p.C, p.Cc, p.soff);
    dim3 gf((B * p.Cc + 255) / 256, 3);
    stats_final_all<<<gf, 256, 0, st>>>(p.N, p.C, p.Cc, B, p.soff);

    int totQ = B * p.N * p.Cc;
    dim3 gp((totQ + 255) / 256, 2);
    prep_split_affine<<<gp, 256, 0, st>>>(cc, sc, totQ, p.Cc, p.N * p.Cc, p.soff, p.qoff);

    dim3 gw(p.N / 32, p.C / 32, B);
    prep_w<<<gw, dim3(32, 8), 0, st>>>(stp, p.N, p.C, p.woff);

    dim3 g1(p.N / 128, p.N / 128, B);
    gemm_f16<0><<<g1, 256, 2 * 3 * 128 * 48, st>>>(p.N, p.N, p.Cc, p.qoff, p.qoff, p.scoff,
                                                   nullptr, nullptr, 0.f, 0);

    softmax_rows<<<B * p.N, 256, p.N * sizeof(float), st>>>(p.N, p.scoff);

    float inv_count = 1.0f / ((float)B * p.N * p.C);
    dim3 g2((2 * p.C) / 128, p.N / 128, B);
    gemm_f16<1><<<g2, 256, 2 * 2 * 128 * 80, st>>>(p.N, 2 * p.C, p.N, p.scoff, p.woff, 0,
                                                   c, cs, inv_count, p.soff);
}

extern "C" void kernel_launch(void* const* d_in, const int* in_sizes, int n_in,
                              void* d_out, int out_size) {
    (void)in_sizes; (void)n_in; (void)out_size;

    static bool s_init = false;
    static cudaStream_t s_aux;
    static cudaEvent_t ev_fork, ev_join;
    if (!s_init) {
        cudaStreamCreateWithFlags(&s_aux, cudaStreamNonBlocking);
        cudaEventCreateWithFlags(&ev_fork, cudaEventDisableTiming);
        cudaEventCreateWithFlags(&ev_join, cudaEventDisableTiming);
        s_init = true;
    }

    // per-scale buffer offsets (elements)
    ScaleP ps[3] = {
        { 0, 1, 2, 3, 4, 4096, 256,  448, 0,        0,        0,        0      },
        { 5, 6, 7, 8, 9, 1024, 512,  960, 7340032,  8388608,  67108864, SMAX   },
        {10,11,12,13,14, 256, 512, 1472, 11272192, 12582912, 71303168, 2*SMAX },
    };

    zero_loss_kernel<<<1, 1>>>();

    // fork aux stream off the capture-origin (default) stream
    cudaEventRecord(ev_fork, 0);
    cudaStreamWaitEvent(s_aux, ev_fork, 0);

    run_scale(ps[0], d_in, 0);       // big scale on main stream
    run_scale(ps[1], d_in, s_aux);   // smaller scales overlap on aux
    run_scale(ps[2], d_in, s_aux);

    // join
    cudaEventRecord(ev_join, s_aux);
    cudaStreamWaitEvent(0, ev_join, 0);

    write_out_kernel<<<1, 1>>>((float*)d_out);
}

// round 17
// speedup vs baseline: 1.4349x; 1.3519x over previous
#include <cuda_runtime.h>
#include <cuda_fp16.h>
#include <cstdint>
#include <math.h>

#define EPS_VAR 1e-9f
#define SMAX (4*1472)

// ---------------- scratch (static device globals; no allocation) ----------------
// Device globals are ONLY referenced from device code (never passed as kernel
// args from host: host would pass the host shadow address, ATS dereferences it).
// Arrays hold all three scales at disjoint offsets so scales can run concurrently.
__device__ float  g_scores[71565312];            // fp32 scores (all scales)
__device__ __half g_Ahi[71565312];               // softmax probs (fp16)
__device__ __half g_Qhi[13631488];
__device__ __half g_Khi[13631488];
__device__ __half g_Whi[13631488];               // [V^T ; (V^2)^T]
__device__ float  g_MT[13631488];                // [M | T] outputs
__device__ float g_sum_q[3*SMAX], g_ss_q[3*SMAX], g_aq[3*SMAX], g_bq[3*SMAX];
__device__ float g_sum_k[3*SMAX], g_ss_k[3*SMAX], g_ak[3*SMAX], g_bk[3*SMAX];
__device__ float g_sum_c[3*SMAX], g_ss_c[3*SMAX], g_ac[3*SMAX], g_bc[3*SMAX];
__device__ double g_loss;

// ---------------- PTX helpers (sm_80-level baseline features only) ----------------
__device__ __forceinline__ uint32_t smem_u32(const void* p){
    uint32_t a; asm("{ .reg .u64 t; cvta.to.shared.u64 t, %1; cvt.u32.u64 %0, t; }" : "=r"(a) : "l"(p)); return a;
}
__device__ __forceinline__ void cp_async16(uint32_t dst, const void* src){
    asm volatile("cp.async.cg.shared.global [%0], [%1], 16;" :: "r"(dst), "l"(src) : "memory");
}
#define CP_COMMIT() asm volatile("cp.async.commit_group;" ::: "memory")
#define CP_WAIT(n)  asm volatile("cp.async.wait_group %0;" :: "n"(n) : "memory")

__device__ __forceinline__ void ldsm4(uint32_t* r, uint32_t addr){
    asm volatile("ldmatrix.sync.aligned.m8n8.x4.shared.b16 {%0,%1,%2,%3}, [%4];"
        : "=r"(r[0]), "=r"(r[1]), "=r"(r[2]), "=r"(r[3]) : "r"(addr));
}
__device__ __forceinline__ void ldsm2(uint32_t* r, uint32_t addr){
    asm volatile("ldmatrix.sync.aligned.m8n8.x2.shared.b16 {%0,%1}, [%2];"
        : "=r"(r[0]), "=r"(r[1]) : "r"(addr));
}
__device__ __forceinline__ void mma_f16(float* c, const uint32_t* a, const uint32_t* b){
    asm volatile("mma.sync.aligned.m16n8k16.row.col.f32.f16.f16.f32 "
        "{%0,%1,%2,%3}, {%4,%5,%6,%7}, {%8,%9}, {%0,%1,%2,%3};"
        : "+f"(c[0]), "+f"(c[1]), "+f"(c[2]), "+f"(c[3])
        : "r"(a[0]), "r"(a[1]), "r"(a[2]), "r"(a[3]), "r"(b[0]), "r"(b[1]));
}

// ---------------- small kernels ----------------
__global__ void zero_loss_kernel() { g_loss = 0.0; }

__global__ void zero_sums_kernel(int soff) {
    int i = blockIdx.x * blockDim.x + threadIdx.x;
    if (i < SMAX) {
        g_sum_q[soff + i] = 0.f; g_ss_q[soff + i] = 0.f;
        g_sum_k[soff + i] = 0.f; g_ss_k[soff + i] = 0.f;
        g_sum_c[soff + i] = 0.f; g_ss_c[soff + i] = 0.f;
    }
}

// merged stats over q (comb_c), k (comb_s), c (content); blockIdx.z selects
__global__ void stats_partial_all(const float* __restrict__ cc, const float* __restrict__ sc,
                                  const float* __restrict__ cv,
                                  int N, int C, int Cc, int soff) {
    int which = blockIdx.z;
    const float* x = (which == 0) ? cc : (which == 1) ? sc : cv;
    int Cx = (which == 2) ? C : Cc;
    float* gsum = ((which == 0) ? g_sum_q : (which == 1) ? g_sum_k : g_sum_c) + soff;
    float* gss  = ((which == 0) ? g_ss_q  : (which == 1) ? g_ss_k  : g_ss_c) + soff;
    int b = blockIdx.x, chunk = blockIdx.y;
    int r0 = chunk * 8;
    for (int c = threadIdx.x; c < Cx; c += blockDim.x) {
        float s = 0.f, ss = 0.f;
        const float* p = x + ((size_t)b * N + r0) * Cx + c;
        #pragma unroll
        for (int r = 0; r < 8; r++) {
            float v = p[(size_t)r * Cx];
            s += v; ss = fmaf(v, v, ss);
        }
        atomicAdd(&gsum[b * Cx + c], s);
        atomicAdd(&gss[b * Cx + c], ss);
    }
}

__global__ void stats_final_all(int N, int C, int Cc, int B, int soff) {
    int which = blockIdx.y;
    int Cx = (which == 2) ? C : Cc;
    const float* gsum = ((which == 0) ? g_sum_q : (which == 1) ? g_sum_k : g_sum_c) + soff;
    const float* gss  = ((which == 0) ? g_ss_q  : (which == 1) ? g_ss_k  : g_ss_c) + soff;
    float* ga = ((which == 0) ? g_aq : (which == 1) ? g_ak : g_ac) + soff;
    float* gb = ((which == 0) ? g_bq : (which == 1) ? g_bk : g_bc) + soff;
    int i = blockIdx.x * blockDim.x + threadIdx.x;
    if (i < B * Cx) {
        float invN = 1.0f / (float)N;
        float mean = gsum[i] * invN;
        float var  = gss[i] * invN - mean * mean;
        float r = rsqrtf(var + 1e-5f);
        ga[i] = r;
        gb[i] = -mean * r;
    }
}

// normalize fp32 -> fp16 (pure fp16 QK; no lo terms)
// blockIdx.y: 0 = comb_c -> Q, 1 = comb_s -> K
__global__ void prep_split_affine(const float* __restrict__ xq, const float* __restrict__ xk,
                                  int total, int C, int perBatch, int soff, size_t qoff) {
    int which = blockIdx.y;
    const float* x  = (which == 0) ? xq : xk;
    const float* ga = ((which == 0) ? g_aq : g_ak) + soff;
    const float* gb = ((which == 0) ? g_bq : g_bk) + soff;
    __half* dst = ((which == 0) ? g_Qhi : g_Khi) + qoff;
    int i = blockIdx.x * blockDim.x + threadIdx.x;
    if (i >= total) return;
    int b = i / perBatch;
    int ch = i % C;
    float y = fmaf(x[i], ga[b * C + ch], gb[b * C + ch]);
    dst[i] = __float2half(y);
}

// W = [V^T ; (V^2)^T]  (2C x N per batch), fp16
__global__ void prep_w(const float* __restrict__ v, int N, int C, size_t woff) {
    __shared__ float tile[32][33];
    int b = blockIdx.z;
    int j0 = blockIdx.x * 32, c0 = blockIdx.y * 32;
    int tx = threadIdx.x, ty = threadIdx.y;  // 32 x 8
    const float* vb = v + (size_t)b * N * C;
    #pragma unroll
    for (int r = 0; r < 4; r++)
        tile[ty + 8 * r][tx] = vb[(size_t)(j0 + ty + 8 * r) * C + c0 + tx];
    __syncthreads();
    __half* w = g_Whi + woff + (size_t)b * 2 * C * N;
    #pragma unroll
    for (int r = 0; r < 4; r++) {
        int c = c0 + ty + 8 * r, j = j0 + tx;
        float val = tile[tx][ty + 8 * r];
        w[(size_t)c * N + j] = __float2half(val);
        w[(size_t)(C + c) * N + j] = __float2half(val * val);
    }
}

// ---------------- mma.sync fp16 GEMM: D = X * Y^T (1-term both modes) ----------------
// MODE 0: X = Qn fp16 (Kg=Cc), Y = Kn, D = g_scores (fp32).
// MODE 1: X = A  (Kg=N),       Y = W,  D = g_MT (fp32).
// 2 tiles/stage, KCH=32, TROWB=80 -> 2*2*10240 = 40960B smem (< 48KB default).
// Bank-conflict check (8-row ldmatrix phase): words 20r mod 32 all distinct.

template<int MODE>
__global__ __launch_bounds__(256)
void gemm_f16(int Mg, int Ng, int Kg, size_t xoff, size_t yoff, size_t doff) {
    constexpr int KCH = 32;
    constexpr int TROWB = 80;
    constexpr int TILE_BYTES = 128 * TROWB;
    constexpr int STAGE_BYTES = 2 * TILE_BYTES;
    extern __shared__ char smem[];
    uint32_t sb = smem_u32(smem);
    int tid = threadIdx.x;
    int wid = tid >> 5, lane = tid & 31;
    int g = lane >> 2, t = lane & 3;
    int warp_m0 = (wid >> 2) << 6;   // 0 or 64
    int warp_n0 = (wid & 3) << 5;    // 0,32,64,96
    int b = blockIdx.z;
    int bi = blockIdx.y * 128, bj = blockIdx.x * 128;

    const __half* Xp = ((MODE == 0) ? g_Qhi : g_Ahi) + xoff;
    const __half* Yp = ((MODE == 0) ? g_Khi : g_Whi) + yoff;
    float* D = ((MODE == 0) ? g_scores : g_MT) + doff;

    const __half* srcs[2];
    srcs[0] = Xp + (size_t)b * Mg * Kg + (size_t)bi * Kg;
    srcs[1] = Yp + (size_t)b * Ng * Kg + (size_t)bj * Kg;

    float acc[4][4][4];
    #pragma unroll
    for (int i = 0; i < 4; i++)
        #pragma unroll
        for (int j = 0; j < 4; j++)
            #pragma unroll
            for (int k = 0; k < 4; k++) acc[i][j][k] = 0.f;

    int nch = Kg / KCH;

    uint32_t a_off = (uint32_t)((warp_m0 + (lane & 15)) * TROWB + (lane >> 4) * 16);
    uint32_t b_off = (uint32_t)((warp_n0 + (lane & 7)) * TROWB + ((lane >> 3) & 1) * 16);

    auto load_chunk = [&](uint32_t sbase, int k0) {
        // 512 16B vectors per tile-pair stage: 2 tiles x 128 rows x 4 halves
        #pragma unroll
        for (int a = 0; a < 2; a++) {
            #pragma unroll
            for (int v = 0; v < 2; v++) {
                int idx = tid + v * 256;
                int r = idx >> 2, h = idx & 3;
                cp_async16(sbase + a * TILE_BYTES + r * TROWB + h * 16,
                           srcs[a] + (size_t)r * Kg + k0 + h * 8);
            }
        }
    };

    load_chunk(sb, 0);
    CP_COMMIT();

    for (int i = 0; i < nch; i++) {
        uint32_t stage = (uint32_t)(i & 1) * STAGE_BYTES;
        if (i + 1 < nch) {
            load_chunk(sb + (uint32_t)((i + 1) & 1) * STAGE_BYTES, (i + 1) * KCH);
            CP_COMMIT();
            CP_WAIT(1);
        } else {
            CP_WAIT(0);
        }
        __syncthreads();

        uint32_t sA = sb + stage;
        uint32_t sB = sA + TILE_BYTES;
        #pragma unroll
        for (int ks = 0; ks < 2; ks++) {
            uint32_t kso = (uint32_t)(ks * 32);
            uint32_t ah[4][4], bh[4][2];
            #pragma unroll
            for (int mi = 0; mi < 4; mi++)
                ldsm4(ah[mi], sA + a_off + kso + mi * 16 * TROWB);
            #pragma unroll
            for (int ni = 0; ni < 4; ni++)
                ldsm2(bh[ni], sB + b_off + kso + ni * 8 * TROWB);
            #pragma unroll
            for (int mi = 0; mi < 4; mi++)
                #pragma unroll
                for (int ni = 0; ni < 4; ni++)
                    mma_f16(acc[mi][ni], ah[mi], bh[ni]);
        }
        __syncthreads();
    }

    float* db = D + (size_t)b * Mg * Ng;
    #pragma unroll
    for (int mi = 0; mi < 4; mi++) {
        int gr = bi + warp_m0 + mi * 16 + g;
        #pragma unroll
        for (int ni = 0; ni < 4; ni++) {
            int gc = bj + warp_n0 + ni * 8 + t * 2;
            float2 v0 = make_float2(acc[mi][ni][0], acc[mi][ni][1]);
            float2 v1 = make_float2(acc[mi][ni][2], acc[mi][ni][3]);
            *reinterpret_cast<float2*>(db + (size_t)gr * Ng + gc) = v0;
            *reinterpret_cast<float2*>(db + (size_t)(gr + 8) * Ng + gc) = v1;
        }
    }
}

// ---------------- row softmax: fp32 scores -> fp16 probs (vectorized) ----------------
__global__ void softmax_rows(int N, size_t scoff) {
    extern __shared__ float srow[];
    __shared__ float red[33];
    size_t row = blockIdx.x;
    const float4* p4 = reinterpret_cast<const float4*>(g_scores + scoff + row * (size_t)N);
    int tid = threadIdx.x, bd = blockDim.x;
    int n4 = N >> 2;

    float m = -1e30f;
    for (int j = tid; j < n4; j += bd) {
        float4 v = p4[j];
        *reinterpret_cast<float4*>(srow + 4 * j) = v;
        m = fmaxf(m, fmaxf(fmaxf(v.x, v.y), fmaxf(v.z, v.w)));
    }
    #pragma unroll
    for (int o = 16; o > 0; o >>= 1) m = fmaxf(m, __shfl_xor_sync(0xffffffffu, m, o));
    if ((tid & 31) == 0) red[tid >> 5] = m;
    __syncthreads();
    if (tid < 32) {
        float v = (tid < (bd >> 5)) ? red[tid] : -1e30f;
        #pragma unroll
        for (int o = 16; o > 0; o >>= 1) v = fmaxf(v, __shfl_xor_sync(0xffffffffu, v, o));
        if (tid == 0) red[32] = v;
    }
    __syncthreads();
    m = red[32];

    float s = 0.f;
    for (int j = tid; j < n4; j += bd) {
        float4 v = *reinterpret_cast<float4*>(srow + 4 * j);
        v.x = __expf(v.x - m); v.y = __expf(v.y - m);
        v.z = __expf(v.z - m); v.w = __expf(v.w - m);
        *reinterpret_cast<float4*>(srow + 4 * j) = v;
        s += (v.x + v.y) + (v.z + v.w);
    }
    __syncthreads();
    #pragma unroll
    for (int o = 16; o > 0; o >>= 1) s += __shfl_xor_sync(0xffffffffu, s, o);
    if ((tid & 31) == 0) red[tid >> 5] = s;
    __syncthreads();
    if (tid < 32) {
        float v = (tid < (bd >> 5)) ? red[tid] : 0.f;
        #pragma unroll
        for (int o = 16; o > 0; o >>= 1) v += __shfl_xor_sync(0xffffffffu, v, o);
        if (tid == 0) red[32] = v;
    }
    __syncthreads();
    float inv = 1.0f / red[32];
    __half2* a2 = reinterpret_cast<__half2*>(g_Ahi + scoff + row * (size_t)N);
    int n2 = N >> 1;
    for (int j = tid; j < n2; j += bd)
        a2[j] = __floats2half2_rn(srow[2 * j] * inv, srow[2 * j + 1] * inv);
}

// ---------------- loss epilogue from [M|T] ----------------
__global__ void loss_epilogue(const float* __restrict__ cin, const float* __restrict__ cs,
                              int N, int C, float inv_count, int total,
                              size_t mtoff, int soff) {
    int i = blockIdx.x * blockDim.x + threadIdx.x;
    float local = 0.f;
    if (i < total) {
        int c = i % C;
        int r = i / C;          // = b*N + n
        int b = r / N;
        const float* mt = g_MT + mtoff;
        float m = mt[(size_t)r * 2 * C + c];
        float t = mt[(size_t)r * 2 * C + C + c];
        float s2 = t - m * m;
        float s = sqrtf(fmaxf(s2, EPS_VAR));
        float nc = fmaf(cin[i], g_ac[soff + b * C + c], g_bc[soff + b * C + c]);
        float aat = fmaf(s, nc, m);
        float d = cs[i] - aat;
        local = d * d * inv_count;
    }
    #pragma unroll
    for (int o = 16; o > 0; o >>= 1) local += __shfl_xor_sync(0xffffffffu, local, o);
    __shared__ float red[8];
    int tid = threadIdx.x;
    if ((tid & 31) == 0) red[tid >> 5] = local;
    __syncthreads();
    if (tid == 0) {
        float t = 0.f;
        #pragma unroll
        for (int k = 0; k < 8; k++) t += red[k];
        atomicAdd(&g_loss, (double)t);
    }
}

__global__ void write_out_kernel(float* out) { out[0] = (float)g_loss; }

// ---------------- host launcher ----------------
struct ScaleP { int i_cs, i_c, i_s, i_cc, i_sc, N, C, Cc; size_t qoff, woff, scoff; int soff; };

static void run_scale(const ScaleP& p, void* const* d_in, cudaStream_t st) {
    const int B = 4;
    const float* cs = (const float*)d_in[p.i_cs];
    const float* c  = (const float*)d_in[p.i_c];
    const float* stp= (const float*)d_in[p.i_s];
    const float* cc = (const float*)d_in[p.i_cc];
    const float* sc = (const float*)d_in[p.i_sc];

    zero_sums_kernel<<<(SMAX + 255) / 256, 256, 0, st>>>(p.soff);

    dim3 gs(B, p.N / 8, 3);
    stats_partial_all<<<gs, 256, 0, st>>>(cc, sc, c, p.N, p.C, p.Cc, p.soff);
    dim3 gf((B * p.Cc + 255) / 256, 3);
    stats_final_all<<<gf, 256, 0, st>>>(p.N, p.C, p.Cc, B, p.soff);

    int totQ = B * p.N * p.Cc;
    dim3 gp((totQ + 255) / 256, 2);
    prep_split_affine<<<gp, 256, 0, st>>>(cc, sc, totQ, p.Cc, p.N * p.Cc, p.soff, p.qoff);

    dim3 gw(p.N / 32, p.C / 32, B);
    prep_w<<<gw, dim3(32, 8), 0, st>>>(stp, p.N, p.C, p.woff);

    dim3 g1(p.N / 128, p.N / 128, B);
    gemm_f16<0><<<g1, 256, 2 * 2 * 128 * 80, st>>>(p.N, p.N, p.Cc, p.qoff, p.qoff, p.scoff);

    softmax_rows<<<B * p.N, 256, p.N * sizeof(float), st>>>(p.N, p.scoff);

    dim3 g2((2 * p.C) / 128, p.N / 128, B);
    gemm_f16<1><<<g2, 256, 2 * 2 * 128 * 80, st>>>(p.N, 2 * p.C, p.N, p.scoff, p.woff, p.woff);

    int tot = B * p.N * p.C;
    float inv_count = 1.0f / (float)tot;
    loss_epilogue<<<(tot + 255) / 256, 256, 0, st>>>(c, cs, p.N, p.C, inv_count, tot, p.woff, p.soff);
}

extern "C" void kernel_launch(void* const* d_in, const int* in_sizes, int n_in,
                              void* d_out, int out_size) {
    (void)in_sizes; (void)n_in; (void)out_size;

    static bool s_init = false;
    static cudaStream_t s_aux;
    static cudaEvent_t ev_fork, ev_join;
    if (!s_init) {
        cudaStreamCreateWithFlags(&s_aux, cudaStreamNonBlocking);
        cudaEventCreateWithFlags(&ev_fork, cudaEventDisableTiming);
        cudaEventCreateWithFlags(&ev_join, cudaEventDisableTiming);
        s_init = true;
    }

    // per-scale buffer offsets (elements)
    ScaleP ps[3] = {
        { 0, 1, 2, 3, 4, 4096, 256,  448, 0,        0,        0,        0      },
        { 5, 6, 7, 8, 9, 1024, 512,  960, 7340032,  8388608,  67108864, SMAX   },
        {10,11,12,13,14, 256, 512, 1472, 11272192, 12582912, 71303168, 2*SMAX },
    };

    zero_loss_kernel<<<1, 1>>>();

    // fork aux stream off the capture-origin (default) stream
    cudaEventRecord(ev_fork, 0);
    cudaStreamWaitEvent(s_aux, ev_fork, 0);

    run_scale(ps[0], d_in, 0);       // big scale on main stream
    run_scale(ps[1], d_in, s_aux);   // smaller scales overlap on aux
    run_scale(ps[2], d_in, s_aux);

    // join
    cudaEventRecord(ev_join, s_aux);
    cudaStreamWaitEvent(0, ev_join, 0);

    write_out_kernel<<<1, 1>>>((float*)d_out);
}